// round 1
// baseline (speedup 1.0000x reference)
#include <cuda_runtime.h>
#include <cstdint>

// Problem constants
#define BB 1024
#define TT 4096
#define LL 30
#define HH 32
#define PP 2

// ---------------------------------------------------------------------------
// Accurate-enough tanh built from MUFU ex2/rcp (abs err ~1e-7), independent of
// compiler fast-math flags. tanh(x) = 1 - 2/(exp2(2*log2e*x)+1).
// ---------------------------------------------------------------------------
__device__ __forceinline__ float ex2f(float x) {
    float r; asm("ex2.approx.ftz.f32 %0, %1;" : "=f"(r) : "f"(x)); return r;
}
__device__ __forceinline__ float rcpf(float x) {
    float r; asm("rcp.approx.ftz.f32 %0, %1;" : "=f"(r) : "f"(x)); return r;
}
__device__ __forceinline__ float tanh_acc(float x) {
    const float C = 2.885390081777927f;  // 2*log2(e)
    float e = ex2f(fminf(x * C, 60.0f));
    return 1.0f - 2.0f * rcpf(e + 1.0f);
}

// ---------------------------------------------------------------------------
// Kernel 1: encoder + sequential Euler scan.
// 4 threads cooperate per batch element (8 hidden units each), dz reduced with
// 2 butterfly shuffles (xor 1, xor 2) so all 4 lanes hold identical z.
// z trajectory is written straight into the z region of d_out, (B,T,P) layout.
// ---------------------------------------------------------------------------
__global__ void __launch_bounds__(128, 1)
scan_kernel(const float* __restrict__ x,
            const float* __restrict__ ew1, const float* __restrict__ eb1,
            const float* __restrict__ ew2, const float* __restrict__ eb2,
            const float* __restrict__ fw1, const float* __restrict__ fb1,
            const float* __restrict__ fw2, const float* __restrict__ fb2,
            float* __restrict__ out)
{
    const int g = blockIdx.x * blockDim.x + threadIdx.x;   // 0..4095
    const int b = g >> 2;
    const int q = g & 3;
    const int j0 = q * 8;
    const float C = 2.885390081777927f;  // 2*log2(e)

    // --- Register-resident ODE weights for this thread's 8 hidden units ---
    float w1a[8], w1b[8], b1s[8], w2a[8], w2b[8];
    float S0 = 0.f, S1 = 0.f;            // sum of w2 over my slice (for 1-2r)
#pragma unroll
    for (int i = 0; i < 8; i++) {
        int j = j0 + i;
        w1a[i] = fw1[j]      * C;        // f_w1[0][j], pre-scaled to exp2 domain
        w1b[i] = fw1[HH + j] * C;        // f_w1[1][j]
        b1s[i] = fb1[j]      * C;
        w2a[i] = fw2[j * PP + 0];
        w2b[i] = fw2[j * PP + 1];
        S0 += w2a[i];
        S1 += w2b[i];
    }
    if (q == 0) { S0 += fb2[0]; S1 += fb2[1]; }  // fold b2 into one lane's S

    // --- Encoder: z0 = tanh(x[b,:30] @ ew1 + eb1) @ ew2 + eb2 ---
    float z1, z2;
    {
        float acc0 = 0.f, acc1 = 0.f;
        const float* xb = x + (size_t)b * TT;
#pragma unroll
        for (int i = 0; i < 8; i++) {
            int j = j0 + i;
            float u = eb1[j];
#pragma unroll
            for (int l = 0; l < LL; l++)
                u = fmaf(xb[l], ew1[l * HH + j], u);
            float th = tanh_acc(u);
            acc0 = fmaf(th, ew2[j * PP + 0], acc0);
            acc1 = fmaf(th, ew2[j * PP + 1], acc1);
        }
        acc0 += __shfl_xor_sync(0xffffffffu, acc0, 1);
        acc1 += __shfl_xor_sync(0xffffffffu, acc1, 1);
        acc0 += __shfl_xor_sync(0xffffffffu, acc0, 2);
        acc1 += __shfl_xor_sync(0xffffffffu, acc1, 2);
        z1 = acc0 + eb2[0];
        z2 = acc1 + eb2[1];
    }

    // z region of d_out: after xhat (B*T) and a (B*T*P)  ->  offset 3*B*T floats
    float2* zo = reinterpret_cast<float2*>(out + 3ull * BB * TT) + (size_t)b * TT;
    if (q == 0) zo[0] = make_float2(z1, z2);

    // --- Sequential Euler scan: 4095 dependent steps ---
    for (int t = 1; t < TT; ++t) {
        // hidden pre-activations (already in exp2 domain), e = exp(2u)+1
        float e[8];
#pragma unroll
        for (int i = 0; i < 8; i++) {
            float u = fmaf(z1, w1a[i], fmaf(z2, w1b[i], b1s[i]));
            e[i] = ex2f(fminf(u, 60.0f)) + 1.0f;
        }
        // paired reciprocals: 1 MUFU.RCP serves two hidden units
        // tanh_j = 1 - 2*r_j;  sum w2*tanh = S - 2*sum(w2*r)
        float a0a = 0.f, a0b = 0.f, a1a = 0.f, a1b = 0.f;
#pragma unroll
        for (int i = 0; i < 8; i += 2) {
            float pr = rcpf(e[i] * e[i + 1]);
            float r0 = pr * e[i + 1];
            float r1 = pr * e[i];
            a0a = fmaf(r0, w2a[i],     a0a);
            a1a = fmaf(r0, w2b[i],     a1a);
            a0b = fmaf(r1, w2a[i + 1], a0b);
            a1b = fmaf(r1, w2b[i + 1], a1b);
        }
        float p0 = fmaf(a0a + a0b, -2.0f, S0);
        float p1 = fmaf(a1a + a1b, -2.0f, S1);
        // reduce across the 4 lanes of this batch (bit-identical in all lanes)
        p0 += __shfl_xor_sync(0xffffffffu, p0, 1);
        p1 += __shfl_xor_sync(0xffffffffu, p1, 1);
        p0 += __shfl_xor_sync(0xffffffffu, p0, 2);
        p1 += __shfl_xor_sync(0xffffffffu, p1, 2);
        z1 += p0;
        z2 += p1;
        if (q == 0) zo[t] = make_float2(z1, z2);
    }
}

// ---------------------------------------------------------------------------
// Kernel 2: parallel epilogue. One thread per (b,t).
// kappa = tanh(z); a = [k1*(1-k2), k2]; xhat[t>=P] = a . phi
// All accesses coalesced float2 / float.
// ---------------------------------------------------------------------------
__global__ void __launch_bounds__(256)
post_kernel(const float* __restrict__ phi, float* __restrict__ out)
{
    size_t idx = (size_t)blockIdx.x * blockDim.x + threadIdx.x;  // = b*T + t
    if (idx >= (size_t)BB * TT) return;
    int t = (int)(idx & (TT - 1));

    float2 z = reinterpret_cast<const float2*>(out + 3ull * BB * TT)[idx];
    float k1 = tanh_acc(z.x);
    float k2 = tanh_acc(z.y);
    float a0 = k1 * (1.0f - k2);
    float a1 = k2;
    reinterpret_cast<float2*>(out + 1ull * BB * TT)[idx] = make_float2(a0, a1);

    float xh = 0.0f;
    if (t >= PP) {
        float2 ph = reinterpret_cast<const float2*>(phi)[idx];
        xh = fmaf(a0, ph.x, a1 * ph.y);
    }
    out[idx] = xh;
}

// ---------------------------------------------------------------------------
extern "C" void kernel_launch(void* const* d_in, const int* in_sizes, int n_in,
                              void* d_out, int out_size)
{
    const float* x   = (const float*)d_in[0];
    const float* phi = (const float*)d_in[1];
    const float* ew1 = (const float*)d_in[2];
    const float* eb1 = (const float*)d_in[3];
    const float* ew2 = (const float*)d_in[4];
    const float* eb2 = (const float*)d_in[5];
    const float* fw1 = (const float*)d_in[6];
    const float* fb1 = (const float*)d_in[7];
    const float* fw2 = (const float*)d_in[8];
    const float* fb2 = (const float*)d_in[9];
    float* out = (float*)d_out;

    // Scan: 4096 threads = 4 per batch element; 32 blocks x 128 -> 1 warp/SMSP
    scan_kernel<<<32, 128>>>(x, ew1, eb1, ew2, eb2, fw1, fb1, fw2, fb2, out);

    // Epilogue: one thread per (b,t)
    int nblk = (BB * TT) / 256;
    post_kernel<<<nblk, 256>>>(phi, out);
}

// round 3
// speedup vs baseline: 1.1626x; 1.1626x over previous
#include <cuda_runtime.h>
#include <cstdint>

// Problem constants
#define BB 1024
#define TT 4096
#define LL 30
#define HH 32
#define PP 2

// ---------------------------------------------------------------------------
// Accurate tanh pieces from MUFU ex2/rcp (abs err ~1e-7).
// tanh(x) = 1 - 2/(exp2(2*log2e*x)+1).
// ---------------------------------------------------------------------------
__device__ __forceinline__ float ex2f(float x) {
    float r; asm("ex2.approx.ftz.f32 %0, %1;" : "=f"(r) : "f"(x)); return r;
}
__device__ __forceinline__ float rcpf(float x) {
    float r; asm("rcp.approx.ftz.f32 %0, %1;" : "=f"(r) : "f"(x)); return r;
}
__device__ __forceinline__ float tanh_acc(float x) {
    const float C = 2.885390081777927f;  // 2*log2(e)
    float e = ex2f(fminf(x * C, 30.0f));
    return 1.0f - 2.0f * rcpf(e + 1.0f);
}

// ---------------------------------------------------------------------------
// Kernel 1: encoder + sequential Euler scan.
// 8 lanes cooperate per batch element (4 hidden units each). Reduction over
// the 8 lanes is a FLAT butterfly: 7 independent shfl_xor of the same value
// (masks 1..7) + an add tree, so only ONE shuffle latency sits on the chain.
// 128 blocks x 64 threads -> 256 warps, 1 warp per SMSP on 128 SMs.
// z trajectory written as float4 every 2 steps straight into d_out's z region.
// ---------------------------------------------------------------------------
__global__ void __launch_bounds__(64, 1)
scan_kernel(const float* __restrict__ x,
            const float* __restrict__ ew1, const float* __restrict__ eb1,
            const float* __restrict__ ew2, const float* __restrict__ eb2,
            const float* __restrict__ fw1, const float* __restrict__ fb1,
            const float* __restrict__ fw2, const float* __restrict__ fb2,
            float* __restrict__ out)
{
    const int g = blockIdx.x * 64 + threadIdx.x;   // 0..8191
    const int b = g >> 3;                          // batch element
    const int q = g & 7;                           // lane within chain group
    const int j0 = q * 4;                          // first hidden unit
    const float C = 2.885390081777927f;            // 2*log2(e)

    // --- Register-resident ODE weights for this thread's 4 hidden units ---
    float w1a[4], w1b[4], b1s[4], w2a[4], w2b[4];
    float S0 = 0.f, S1 = 0.f;                      // sum of w2 (for 1-2r trick)
#pragma unroll
    for (int i = 0; i < 4; i++) {
        int j = j0 + i;
        w1a[i] = fw1[j]      * C;                  // pre-scaled to exp2 domain
        w1b[i] = fw1[HH + j] * C;
        b1s[i] = fb1[j]      * C;
        w2a[i] = fw2[j * PP + 0];
        w2b[i] = fw2[j * PP + 1];
        S0 += w2a[i];
        S1 += w2b[i];
    }
    if (q == 0) { S0 += fb2[0]; S1 += fb2[1]; }    // fold b2 into one lane

    // --- Encoder: z0 = tanh(x[b,:30] @ ew1 + eb1) @ ew2 + eb2 ---
    float z1, z2;
    {
        float acc0 = 0.f, acc1 = 0.f;
        const float* xb = x + (size_t)b * TT;
#pragma unroll
        for (int i = 0; i < 4; i++) {
            int j = j0 + i;
            float u = eb1[j];
#pragma unroll
            for (int l = 0; l < LL; l++)
                u = fmaf(xb[l], ew1[l * HH + j], u);
            float th = tanh_acc(u);
            acc0 = fmaf(th, ew2[j * PP + 0], acc0);
            acc1 = fmaf(th, ew2[j * PP + 1], acc1);
        }
        acc0 += __shfl_xor_sync(0xffffffffu, acc0, 1);
        acc1 += __shfl_xor_sync(0xffffffffu, acc1, 1);
        acc0 += __shfl_xor_sync(0xffffffffu, acc0, 2);
        acc1 += __shfl_xor_sync(0xffffffffu, acc1, 2);
        acc0 += __shfl_xor_sync(0xffffffffu, acc0, 4);
        acc1 += __shfl_xor_sync(0xffffffffu, acc1, 4);
        z1 = acc0 + eb2[0];
        z2 = acc1 + eb2[1];
    }

    // z region of d_out: after xhat (B*T) and a (B*T*P) -> offset 3*B*T floats.
    // Stored as float4 = two consecutive (z1,z2) time entries.
    float4* zo4 = reinterpret_cast<float4*>(out + 3ull * BB * TT)
                + (size_t)b * (TT / 2);

    // --- One Euler step: z += W2^T tanh(W1 z + b1) + b2 (DT=1) ---
    auto STEP = [&]() {
        // E_i = exp2(min(u_i,30)) + 1, u already in exp2 domain
        float c0 = fmaf(z2, w1b[0], b1s[0]);
        float c1 = fmaf(z2, w1b[1], b1s[1]);
        float c2 = fmaf(z2, w1b[2], b1s[2]);
        float c3 = fmaf(z2, w1b[3], b1s[3]);
        float E0 = ex2f(fminf(fmaf(z1, w1a[0], c0), 30.f)) + 1.f;
        float E1 = ex2f(fminf(fmaf(z1, w1a[1], c1), 30.f)) + 1.f;
        float E2 = ex2f(fminf(fmaf(z1, w1a[2], c2), 30.f)) + 1.f;
        float E3 = ex2f(fminf(fmaf(z1, w1a[3], c3), 30.f)) + 1.f;
        // paired reciprocals: r_i = 1/E_i, one MUFU.RCP per 2 units
        float pr01 = rcpf(E0 * E1);
        float pr23 = rcpf(E2 * E3);
        float r0 = pr01 * E1, r1 = pr01 * E0;
        float r2 = pr23 * E3, r3 = pr23 * E2;
        // sum w2*tanh = S - 2*sum(w2*r)
        float a0 = fmaf(r1, w2a[1], r0 * w2a[0]) + fmaf(r3, w2a[3], r2 * w2a[2]);
        float a1 = fmaf(r1, w2b[1], r0 * w2b[0]) + fmaf(r3, w2b[3], r2 * w2b[2]);
        float p0 = fmaf(a0, -2.0f, S0);
        float p1 = fmaf(a1, -2.0f, S1);
        // flat butterfly reduction over the 8 lanes of this chain:
        // all 7 shuffles source the ORIGINAL p -> one shuffle latency on chain
        float s01 = __shfl_xor_sync(0xffffffffu, p0, 1);
        float s02 = __shfl_xor_sync(0xffffffffu, p0, 2);
        float s03 = __shfl_xor_sync(0xffffffffu, p0, 3);
        float s04 = __shfl_xor_sync(0xffffffffu, p0, 4);
        float s05 = __shfl_xor_sync(0xffffffffu, p0, 5);
        float s06 = __shfl_xor_sync(0xffffffffu, p0, 6);
        float s07 = __shfl_xor_sync(0xffffffffu, p0, 7);
        float s11 = __shfl_xor_sync(0xffffffffu, p1, 1);
        float s12 = __shfl_xor_sync(0xffffffffu, p1, 2);
        float s13 = __shfl_xor_sync(0xffffffffu, p1, 3);
        float s14 = __shfl_xor_sync(0xffffffffu, p1, 4);
        float s15 = __shfl_xor_sync(0xffffffffu, p1, 5);
        float s16 = __shfl_xor_sync(0xffffffffu, p1, 6);
        float s17 = __shfl_xor_sync(0xffffffffu, p1, 7);
        p0 = ((p0 + s01) + (s02 + s03)) + ((s04 + s05) + (s06 + s07));
        p1 = ((p1 + s11) + (s12 + s13)) + ((s14 + s15) + (s16 + s17));
        z1 += p0;
        z2 += p1;
    };

    // --- 4095 steps, unrolled by 2, one float4 store per 2 time entries ---
#pragma unroll 1
    for (int k = 0; k < 2047; ++k) {
        float az1 = z1, az2 = z2;          // entry 2k
        STEP();                            // entry 2k+1
        if (q == 0) zo4[k] = make_float4(az1, az2, z1, z2);
        STEP();                            // entry 2k+2
    }
    {
        float az1 = z1, az2 = z2;          // entry 4094
        STEP();                            // entry 4095
        if (q == 0) zo4[2047] = make_float4(az1, az2, z1, z2);
    }
}

// ---------------------------------------------------------------------------
// Kernel 2: parallel epilogue. One thread per (b,t).
// kappa = tanh(z); a = [k1*(1-k2), k2]; xhat[t>=P] = a . phi
// ---------------------------------------------------------------------------
__global__ void __launch_bounds__(256)
post_kernel(const float* __restrict__ phi, float* __restrict__ out)
{
    size_t idx = (size_t)blockIdx.x * blockDim.x + threadIdx.x;  // = b*T + t
    if (idx >= (size_t)BB * TT) return;
    int t = (int)(idx & (TT - 1));

    float2 z = reinterpret_cast<const float2*>(out + 3ull * BB * TT)[idx];
    float k1 = tanh_acc(z.x);
    float k2 = tanh_acc(z.y);
    float a0 = k1 * (1.0f - k2);
    float a1 = k2;
    reinterpret_cast<float2*>(out + 1ull * BB * TT)[idx] = make_float2(a0, a1);

    float xh = 0.0f;
    if (t >= PP) {
        float2 ph = reinterpret_cast<const float2*>(phi)[idx];
        xh = fmaf(a0, ph.x, a1 * ph.y);
    }
    out[idx] = xh;
}

// ---------------------------------------------------------------------------
extern "C" void kernel_launch(void* const* d_in, const int* in_sizes, int n_in,
                              void* d_out, int out_size)
{
    const float* x   = (const float*)d_in[0];
    const float* phi = (const float*)d_in[1];
    const float* ew1 = (const float*)d_in[2];
    const float* eb1 = (const float*)d_in[3];
    const float* ew2 = (const float*)d_in[4];
    const float* eb2 = (const float*)d_in[5];
    const float* fw1 = (const float*)d_in[6];
    const float* fb1 = (const float*)d_in[7];
    const float* fw2 = (const float*)d_in[8];
    const float* fb2 = (const float*)d_in[9];
    float* out = (float*)d_out;

    // Scan: 8192 threads = 8 lanes per batch element; 128 blocks x 64 threads
    // -> 256 warps, one per SMSP across 128 SMs.
    scan_kernel<<<128, 64>>>(x, ew1, eb1, ew2, eb2, fw1, fb1, fw2, fb2, out);

    // Epilogue: one thread per (b,t)
    int nblk = (BB * TT) / 256;
    post_kernel<<<nblk, 256>>>(phi, out);
}